// round 15
// baseline (speedup 1.0000x reference)
#include <cuda_runtime.h>
#include <cstdint>

typedef unsigned int u32;

#define T_KD   4.0f
#define Bsz    4096
#define Pn     12
#define DIN    640
#define Dm     128
#define TM     64                      // tile rows per CTA
#define NBLK_G (Bsz / TM)              // 64
#define NTILES ((Pn + 1) * Bsz / TM)   // 832
#define THREADS 256
#define KC1    64                      // layer-1 k-chunk
#define NCH1   (DIN / KC1)             // 10

// ---- SMEM layout (bytes) ----
// misc [0,4096); L1 stages: 2 x { A 16KB + B 32KB } = 96KB
// after L1 (reuse): Hf 32KB @OFF_STG ; B2 stages 2 x 16KB @OFF_STG+32768
#define OFF_STG   4096
#define A_TILE_F  4096                 // floats: [kk8][gmt4][lane32][e4]
#define STG_SZ    49152                // bytes per stage (A 16KB + B 32KB)
#define OFF_HF    OFF_STG
#define OFF_B2    (OFF_STG + 32768)
#define SMEM_TOTAL (OFF_STG + 2 * STG_SZ)   // 102400 bytes

// ---- scratch ----
__device__ float g_buf[Bsz * Dm];
__device__ float p_buf[Pn * Bsz * Dm];
__device__ float part_dil[Bsz];
__device__ float part_dcl[Bsz];

// Mask-based tf32 split: hi = tf32 truncation, lo = exact residual.
__device__ __forceinline__ void split1(float v, u32& h, u32& l) {
    h = __float_as_uint(v) & 0xFFFFE000u;
    l = __float_as_uint(v - __uint_as_float(h));
}

#define MMA(c, a, b) \
    asm volatile("mma.sync.aligned.m16n8k8.row.col.f32.tf32.tf32.f32 " \
        "{%0,%1,%2,%3},{%4,%5,%6,%7},{%8,%9},{%0,%1,%2,%3};" \
        : "+f"((c)[0]), "+f"((c)[1]), "+f"((c)[2]), "+f"((c)[3]) \
        : "r"((a)[0]), "r"((a)[1]), "r"((a)[2]), "r"((a)[3]), \
          "r"((b)[0]), "r"((b)[1]))

// k8 steps [K0,K1): 3-pass tf32 emulation, warp tile 32x32.
// A layout [kk][gmt(4)][lane]{e0..e3}, B layout [kk][gnt(16)][lane]{e0,e1}.
template<int K0, int K1>
__device__ __forceinline__ void gemm_part(
    const float* __restrict__ Ab, const float* __restrict__ Bb,
    float acc[2][4][4], int lane, int gm2, int wn4)
{
#pragma unroll
    for (int kk = K0; kk < K1; kk++) {
        u32 ah[2][4], al[2][4];
#pragma unroll
        for (int mt = 0; mt < 2; mt++) {
            float4 a = *(const float4*)(Ab + (size_t)((kk * 4 + gm2 + mt) * 32 + lane) * 4);
            split1(a.x, ah[mt][0], al[mt][0]);
            split1(a.y, ah[mt][1], al[mt][1]);
            split1(a.z, ah[mt][2], al[mt][2]);
            split1(a.w, ah[mt][3], al[mt][3]);
        }
        u32 bh[4][2], bl[4][2];
#pragma unroll
        for (int nt = 0; nt < 4; nt++) {
            float2 b = *(const float2*)(Bb + (size_t)((kk * 16 + wn4 + nt) * 32 + lane) * 2);
            split1(b.x, bh[nt][0], bl[nt][0]);
            split1(b.y, bh[nt][1], bl[nt][1]);
        }
        // pass-major order: same-acc reuse distance = 8 MMAs
#pragma unroll
        for (int mt = 0; mt < 2; mt++)
#pragma unroll
            for (int nt = 0; nt < 4; nt++) MMA(acc[mt][nt], ah[mt], bh[nt]);
#pragma unroll
        for (int mt = 0; mt < 2; mt++)
#pragma unroll
            for (int nt = 0; nt < 4; nt++) MMA(acc[mt][nt], al[mt], bh[nt]);
#pragma unroll
        for (int mt = 0; mt < 2; mt++)
#pragma unroll
            for (int nt = 0; nt < 4; nt++) MMA(acc[mt][nt], ah[mt], bl[nt]);
    }
}

// rotate (w0..w3) so that wi = v[i^r]; pure SELs, no dynamic indexing
__device__ __forceinline__ void rot4(float4 v, int r,
                                     float& w0, float& w1, float& w2, float& w3)
{
    float a0 = v.x, a1 = v.y, a2 = v.z, a3 = v.w;
    if (r & 1) { float t = a0; a0 = a1; a1 = t; t = a2; a2 = a3; a3 = t; }
    if (r & 2) { float t = a0; a0 = a2; a2 = t; t = a1; a1 = a3; a3 = t; }
    w0 = a0; w1 = a1; w2 = a2; w3 = a3;
}

// fragment-order STS with (kk&3)-rotated issue order (data placement fixed).
// q = k-quad index (0..15 for KC=64, 0..7 for KC=32).
__device__ __forceinline__ void stsA(float* p, int arow, int q, float4 v) {
    const int kk = q >> 1;
    const int r  = kk & 3;
    const int e  = ((q & 1) << 1) | ((arow >> 3) & 1);
    float* base = p + (size_t)((kk * 4 + (arow >> 4)) * 32 + ((arow & 7) << 2)) * 4 + e;
    float w0, w1, w2, w3;
    rot4(v, r, w0, w1, w2, w3);
    base[((0 ^ r) << 2)] = w0;
    base[((1 ^ r) << 2)] = w1;
    base[((2 ^ r) << 2)] = w2;
    base[((3 ^ r) << 2)] = w3;
}
__device__ __forceinline__ void stsB(float* p, int brow, int q, float4 v) {
    const int kk = q >> 1;
    const int r  = kk & 3;
    const int e  = q & 1;
    float* base = p + (size_t)((kk * 16 + (brow >> 3)) * 32 + ((brow & 7) << 2)) * 2 + e;
    float w0, w1, w2, w3;
    rot4(v, r, w0, w1, w2, w3);
    base[((0 ^ r) << 1)] = w0;
    base[((1 ^ r) << 1)] = w1;
    base[((2 ^ r) << 1)] = w2;
    base[((3 ^ r) << 1)] = w3;
}

__global__ void __launch_bounds__(THREADS, 2) embed_kernel(
    const float* __restrict__ ebg, const float* __restrict__ ebp,
    const float* __restrict__ gw1, const float* __restrict__ gb1,
    const float* __restrict__ gw2, const float* __restrict__ gb2,
    const float* __restrict__ pw1, const float* __restrict__ pb1,
    const float* __restrict__ pw2, const float* __restrict__ pb2)
{
    extern __shared__ char sm[];
    float* miscf = (float*)sm;
    float* b1s   = miscf;                 // [128]
    float* b2s   = miscf + 128;           // [128]
    float* rinvs = miscf + 256;           // [64]
    float* parts = miscf + 320;           // [4][64]
    float* Hf    = (float*)(sm + OFF_HF); // 8192 floats (32KB), KC32 A-frag layout

    const int t    = threadIdx.x;
    const int wid  = t >> 5, lane = t & 31;
    const int wm   = wid >> 2, wn = wid & 3;   // wm 0..1, wn 0..3
    const int gm2  = wm * 2,   wn4 = wn * 4;
    const int blk  = blockIdx.x;

    const float *X, *W1, *B1v, *W2, *B2v;
    float* OUT;
    int rowbase;
    if (blk < NBLK_G) {
        X = ebg; W1 = gw1; B1v = gb1; W2 = gw2; B2v = gb2;
        OUT = g_buf; rowbase = blk * TM;
    } else {
        X = ebp; W1 = pw1; B1v = pb1; W2 = pw2; B2v = pb2;
        OUT = p_buf; rowbase = (blk - NBLK_G) * TM;
    }

    if (t < 128) b1s[t] = B1v[t];
    else         b2s[t - 128] = B2v[t - 128];

    // loader indexing: arow0 = t>>3 (0..31), akq = t&7; quads akq and akq+8
    const int arow0 = t >> 3;
    const int akq   = t & 7;
    const float* xptr  = X  + (size_t)(rowbase + arow0) * DIN + akq * 4;
    const float* w1ptr = W1 + (size_t)arow0 * DIN + akq * 4;
    const float* w2ptr = W2 + (size_t)arow0 * Dm  + akq * 4;

    float acc[2][4][4];
#pragma unroll
    for (int a = 0; a < 2; a++)
#pragma unroll
        for (int b = 0; b < 4; b++)
#pragma unroll
            for (int c = 0; c < 4; c++) acc[a][b][c] = 0.f;

    // ---------------- Layer 1: K = 640, 10 chunks of 64 ------------------
    float4 pax[2], pbx[4];
    {
        float* S = (float*)(sm + OFF_STG);
        // round 1: quad akq (cols [akq*4, +4) of chunk 0)
#pragma unroll
        for (int i = 0; i < 2; i++) {
            pax[i] = *(const float4*)(xptr + (size_t)(32 * i) * DIN);
            stsA(S, arow0 + 32 * i, akq, pax[i]);
        }
#pragma unroll
        for (int i = 0; i < 4; i++) {
            pbx[i] = *(const float4*)(w1ptr + (size_t)(32 * i) * DIN);
            stsB(S + A_TILE_F, arow0 + 32 * i, akq, pbx[i]);
        }
        // round 2: quad akq+8 (cols +32)
#pragma unroll
        for (int i = 0; i < 2; i++) {
            pax[i] = *(const float4*)(xptr + (size_t)(32 * i) * DIN + 32);
            stsA(S, arow0 + 32 * i, akq + 8, pax[i]);
        }
#pragma unroll
        for (int i = 0; i < 4; i++) {
            pbx[i] = *(const float4*)(w1ptr + (size_t)(32 * i) * DIN + 32);
            stsB(S + A_TILE_F, arow0 + 32 * i, akq + 8, pbx[i]);
        }
    }
    __syncthreads();

#pragma unroll 1
    for (int c = 0; c < NCH1; c++) {
        const float* S = (const float*)(sm + OFF_STG + (c & 1) * STG_SZ);
        float* N = (float*)(sm + OFF_STG + ((c + 1) & 1) * STG_SZ);
        const int off1 = (c + 1) * KC1;

        if (c < NCH1 - 1) {
#pragma unroll
            for (int i = 0; i < 2; i++)
                pax[i] = *(const float4*)(xptr + (size_t)(32 * i) * DIN + off1);
#pragma unroll
            for (int i = 0; i < 4; i++)
                pbx[i] = *(const float4*)(w1ptr + (size_t)(32 * i) * DIN + off1);
        }
        gemm_part<0, 4>(S, S + A_TILE_F, acc, lane, gm2, wn4);
        if (c < NCH1 - 1) {
#pragma unroll
            for (int i = 0; i < 2; i++) stsA(N, arow0 + 32 * i, akq, pax[i]);
#pragma unroll
            for (int i = 0; i < 4; i++) stsB(N + A_TILE_F, arow0 + 32 * i, akq, pbx[i]);
#pragma unroll
            for (int i = 0; i < 2; i++)
                pax[i] = *(const float4*)(xptr + (size_t)(32 * i) * DIN + off1 + 32);
#pragma unroll
            for (int i = 0; i < 4; i++)
                pbx[i] = *(const float4*)(w1ptr + (size_t)(32 * i) * DIN + off1 + 32);
        }
        gemm_part<4, 8>(S, S + A_TILE_F, acc, lane, gm2, wn4);
        if (c < NCH1 - 1) {
#pragma unroll
            for (int i = 0; i < 2; i++) stsA(N, arow0 + 32 * i, akq + 8, pax[i]);
#pragma unroll
            for (int i = 0; i < 4; i++) stsB(N + A_TILE_F, arow0 + 32 * i, akq + 8, pbx[i]);
        }
        __syncthreads();
    }

    // ------- L1 epilogue: H = relu(acc + b1) -> fp32 KC32 A-frag layout ---
#pragma unroll
    for (int mt = 0; mt < 2; mt++)
#pragma unroll
        for (int nt = 0; nt < 4; nt++)
#pragma unroll
            for (int rr = 0; rr < 4; rr++) {
                const int m = wm * 32 + mt * 16 + (lane >> 2) + 8 * (rr >> 1);
                const int n = wn * 32 + nt * 8 + 2 * (lane & 3) + (rr & 1);
                float y = fmaxf(acc[mt][nt][rr] + b1s[n], 0.f);
                const int idx = ((((n >> 3) * 4 + (m >> 4)) * 32
                                  + (((m & 7) << 2) | (n & 3))) << 2)
                                + (((n & 4) >> 1) | ((m >> 3) & 1));
                Hf[idx] = y;
            }

    // stage B2 chunk 0 (fp32, KC32 layout)
#pragma unroll
    for (int i = 0; i < 4; i++)
        pbx[i] = *(const float4*)(w2ptr + (size_t)(32 * i) * Dm);
    {
        float* S = (float*)(sm + OFF_B2);
#pragma unroll
        for (int i = 0; i < 4; i++) stsB(S, arow0 + 32 * i, akq, pbx[i]);
    }

#pragma unroll
    for (int a = 0; a < 2; a++)
#pragma unroll
        for (int b = 0; b < 4; b++)
#pragma unroll
            for (int c = 0; c < 4; c++) acc[a][b][c] = 0.f;
    __syncthreads();

    // ---------------- Layer 2: K = 128, 4 chunks of 32 --------------------
#pragma unroll 1
    for (int c2 = 0; c2 < 4; c2++) {
        if (c2 < 3) {
#pragma unroll
            for (int i = 0; i < 4; i++)
                pbx[i] = *(const float4*)(w2ptr + (size_t)(32 * i) * Dm + (c2 + 1) * 32);
        }
        const float* S = (const float*)(sm + OFF_B2 + (c2 & 1) * 16384);
        gemm_part<0, 4>(Hf + c2 * 2048, S, acc, lane, gm2, wn4);
        if (c2 < 3) {
            float* N = (float*)(sm + OFF_B2 + ((c2 + 1) & 1) * 16384);
#pragma unroll
            for (int i = 0; i < 4; i++) stsB(N, arow0 + 32 * i, akq, pbx[i]);
        }
        __syncthreads();
    }

    // -------- L2 epilogue: bias, row sum-squares, L2 norm, direct store ----
    float s2[2][2] = {{0.f, 0.f}, {0.f, 0.f}};
#pragma unroll
    for (int mt = 0; mt < 2; mt++)
#pragma unroll
        for (int nt = 0; nt < 4; nt++)
#pragma unroll
            for (int rr = 0; rr < 4; rr++) {
                const int n = wn * 32 + nt * 8 + 2 * (lane & 3) + (rr & 1);
                const float y = acc[mt][nt][rr] + b2s[n];
                acc[mt][nt][rr] = y;
                s2[mt][rr >> 1] += y * y;
            }
#pragma unroll
    for (int mt = 0; mt < 2; mt++)
#pragma unroll
        for (int rH = 0; rH < 2; rH++) {
            float v = s2[mt][rH];
            v += __shfl_xor_sync(0xffffffffu, v, 1);
            v += __shfl_xor_sync(0xffffffffu, v, 2);
            if ((lane & 3) == 0) {
                const int m = wm * 32 + mt * 16 + (lane >> 2) + 8 * rH;
                parts[wn * 64 + m] = v;
            }
        }
    __syncthreads();
    if (t < 64)
        rinvs[t] = rsqrtf(parts[t] + parts[64 + t] + parts[128 + t] + parts[192 + t]);
    __syncthreads();

#pragma unroll
    for (int mt = 0; mt < 2; mt++)
#pragma unroll
        for (int rH = 0; rH < 2; rH++) {
            const int m = wm * 32 + mt * 16 + (lane >> 2) + 8 * rH;
            const float rv = rinvs[m];
            float* orow = OUT + (size_t)(rowbase + m) * Dm;
#pragma unroll
            for (int nt = 0; nt < 4; nt++) {
                const int n = wn * 32 + nt * 8 + 2 * (lane & 3);
                float2 y;
                y.x = acc[mt][nt][rH * 2 + 0] * rv;
                y.y = acc[mt][nt][rH * 2 + 1] * rv;
                *(float2*)(orow + n) = y;
            }
        }
}

// ---------------------------------------------------------------------------
// Loss: one WARP per b, all rows in registers, no smem, no block barriers.
// ---------------------------------------------------------------------------
__device__ __forceinline__ float wredsum(float v) {
#pragma unroll
    for (int o = 16; o; o >>= 1) v += __shfl_xor_sync(0xffffffffu, v, o);
    return v;
}
__device__ __forceinline__ float wredmax(float v) {
#pragma unroll
    for (int o = 16; o; o >>= 1) v = fmaxf(v, __shfl_xor_sync(0xffffffffu, v, o));
    return v;
}
__device__ __forceinline__ float symkl4(const float* u, const float* v) {
    const float iT = 1.0f / T_KD;
    float uu[4], vv[4];
    float mu = -1e30f, mv = -1e30f;
#pragma unroll
    for (int q = 0; q < 4; q++) {
        uu[q] = u[q] * iT; vv[q] = v[q] * iT;
        mu = fmaxf(mu, uu[q]); mv = fmaxf(mv, vv[q]);
    }
    mu = wredmax(mu); mv = wredmax(mv);
    float eu[4], ev[4], su = 0.f, sv = 0.f;
#pragma unroll
    for (int q = 0; q < 4; q++) {
        eu[q] = __expf(uu[q] - mu); su += eu[q];
        ev[q] = __expf(vv[q] - mv); sv += ev[q];
    }
    su = wredsum(su); sv = wredsum(sv);
    const float lsu = __logf(su), lsv = __logf(sv);
    const float isu = 1.f / su,  isv = 1.f / sv;
    float a = 0.f;
#pragma unroll
    for (int q = 0; q < 4; q++) {
        const float la = uu[q] - mu - lsu;
        const float lb = vv[q] - mv - lsv;
        a += (eu[q] * isu - ev[q] * isv) * (la - lb);
    }
    return wredsum(a);
}

__global__ void __launch_bounds__(256) loss_kernel() {
    const int warp = threadIdx.x >> 5, lane = threadIdx.x & 31;
    const int b = blockIdx.x * 8 + warp;

    float g[4], pb[4], p[Pn][4];
    *(float4*)g = *(const float4*)(g_buf + (size_t)b * Dm + lane * 4);
#pragma unroll
    for (int l = 0; l < Pn; l++)
        *(float4*)p[l] = *(const float4*)(p_buf + ((size_t)l * Bsz + b) * Dm + lane * 4);

#pragma unroll
    for (int q = 0; q < 4; q++) {
        float s = 0.f;
#pragma unroll
        for (int l = 0; l < Pn; l++) s += p[l][q];
        pb[q] = s * (1.0f / Pn);
    }

    const float vdil = symkl4(g, pb);

    float dcl = 0.f;
#pragma unroll
    for (int l = 0; l < Pn; l++) {
        float du[4], dv[4];
#pragma unroll
        for (int q = 0; q < 4; q++) {
            float a = g[q]  - p[l][q]; du[q] = a * a;
            float d = pb[q] - p[l][q]; dv[q] = d * d;
        }
        dcl += symkl4(du, dv);
    }

    if (lane == 0) {
        const float sc = (T_KD * T_KD) / (float)Dm;
        part_dil[b] = vdil * sc;
        part_dcl[b] = dcl * sc;
    }
}

// Deterministic fixed-order final reduction
__global__ void __launch_bounds__(256) final_kernel(float* out, int out_size) {
    __shared__ float s1[256], s2[256];
    const int t = threadIdx.x;
    float a = 0.f, c = 0.f;
    for (int i = t; i < Bsz; i += 256) { a += part_dil[i]; c += part_dcl[i]; }
    s1[t] = a; s2[t] = c;
    __syncthreads();
#pragma unroll
    for (int o = 128; o > 0; o >>= 1) {
        if (t < o) { s1[t] += s1[t + o]; s2[t] += s2[t + o]; }
        __syncthreads();
    }
    if (t == 0) {
        if (out_size > 0) out[0] = s1[0];
        if (out_size > 1) out[1] = s2[0] * (1.0f / Pn);
    }
}

extern "C" void kernel_launch(void* const* d_in, const int* in_sizes, int n_in,
                              void* d_out, int out_size) {
    (void)in_sizes; (void)n_in;
    const float* ebg = (const float*)d_in[0];
    const float* ebp = (const float*)d_in[1];
    const float* gw1 = (const float*)d_in[3];
    const float* gb1 = (const float*)d_in[4];
    const float* gw2 = (const float*)d_in[5];
    const float* gb2 = (const float*)d_in[6];
    const float* pw1 = (const float*)d_in[7];
    const float* pb1 = (const float*)d_in[8];
    const float* pw2 = (const float*)d_in[9];
    const float* pb2 = (const float*)d_in[10];

    cudaFuncSetAttribute(embed_kernel,
                         cudaFuncAttributeMaxDynamicSharedMemorySize, SMEM_TOTAL);

    embed_kernel<<<NTILES, THREADS, SMEM_TOTAL>>>(
        ebg, ebp, gw1, gb1, gw2, gb2, pw1, pb1, pw2, pb2);
    loss_kernel<<<Bsz / 8, 256>>>();
    final_kernel<<<1, 256>>>((float*)d_out, out_size);
}

// round 17
// speedup vs baseline: 1.2720x; 1.2720x over previous
#include <cuda_runtime.h>
#include <cstdint>

typedef unsigned int u32;

#define T_KD   4.0f
#define Bsz    4096
#define Pn     12
#define DIN    640
#define Dm     128
#define TM     64                      // tile rows per CTA
#define NBLK_G (Bsz / TM)              // 64
#define NTILES ((Pn + 1) * Bsz / TM)   // 832
#define THREADS 256

// ---- SMEM layout (bytes) ----
#define OFF_STG   4096
#define STG_SZ    24576
#define OFF_HF    OFF_STG
#define OFF_B2    (OFF_STG + 32768)
#define SMEM_TOTAL (OFF_B2 + 32768)    // 69632 bytes

// ---- scratch ----
__device__ float g_buf[Bsz * Dm];
__device__ float p_buf[Pn * Bsz * Dm];
__device__ float part_dil[Bsz];
__device__ float part_dcl[Bsz];

// Mask-based tf32 split: hi = tf32 truncation, lo = exact residual.
__device__ __forceinline__ void split1(float v, u32& h, u32& l) {
    h = __float_as_uint(v) & 0xFFFFE000u;
    l = __float_as_uint(v - __uint_as_float(h));
}
__device__ __forceinline__ u32 hi1(float v) {
    return __float_as_uint(v) & 0xFFFFE000u;
}

#define MMA(c, a, b) \
    asm volatile("mma.sync.aligned.m16n8k8.row.col.f32.tf32.tf32.f32 " \
        "{%0,%1,%2,%3},{%4,%5,%6,%7},{%8,%9},{%0,%1,%2,%3};" \
        : "+f"((c)[0]), "+f"((c)[1]), "+f"((c)[2]), "+f"((c)[3]) \
        : "r"((a)[0]), "r"((a)[1]), "r"((a)[2]), "r"((a)[3]), \
          "r"((b)[0]), "r"((b)[1]))

// one KC=32 chunk: 4 k8 steps, warp tile 32x32.
// THREE=true : 3-pass (hh + lh + hl)  — near-fp32
// THREE=false: 2-pass (hh + lh)       — drops ah*bl (~2^-12 rel), layer 1 only
template<bool THREE>
__device__ __forceinline__ void gemm_chunk(
    const float* __restrict__ Ab, const float* __restrict__ Bb,
    float acc[2][4][4], int lane, int gm2, int wn4)
{
#pragma unroll
    for (int kk = 0; kk < 4; kk++) {
        u32 ah[2][4], al[2][4];
#pragma unroll
        for (int mt = 0; mt < 2; mt++) {
            float4 a = *(const float4*)(Ab + (size_t)((kk * 4 + gm2 + mt) * 32 + lane) * 4);
            split1(a.x, ah[mt][0], al[mt][0]);
            split1(a.y, ah[mt][1], al[mt][1]);
            split1(a.z, ah[mt][2], al[mt][2]);
            split1(a.w, ah[mt][3], al[mt][3]);
        }
        u32 bh[4][2], bl[4][2];
#pragma unroll
        for (int nt = 0; nt < 4; nt++) {
            float2 b = *(const float2*)(Bb + (size_t)((kk * 16 + wn4 + nt) * 32 + lane) * 2);
            if (THREE) {
                split1(b.x, bh[nt][0], bl[nt][0]);
                split1(b.y, bh[nt][1], bl[nt][1]);
            } else {
                bh[nt][0] = hi1(b.x);
                bh[nt][1] = hi1(b.y);
            }
        }
        // pass-major order: same-acc reuse distance = 8 MMAs
#pragma unroll
        for (int mt = 0; mt < 2; mt++)
#pragma unroll
            for (int nt = 0; nt < 4; nt++) MMA(acc[mt][nt], ah[mt], bh[nt]);
#pragma unroll
        for (int mt = 0; mt < 2; mt++)
#pragma unroll
            for (int nt = 0; nt < 4; nt++) MMA(acc[mt][nt], al[mt], bh[nt]);
        if (THREE) {
#pragma unroll
            for (int mt = 0; mt < 2; mt++)
#pragma unroll
                for (int nt = 0; nt < 4; nt++) MMA(acc[mt][nt], ah[mt], bl[nt]);
        }
    }
}

// rotate (w0..w3) so that wi = v[i^kk]; pure SELs, no dynamic indexing
__device__ __forceinline__ void rot4(float4 v, int kk,
                                     float& w0, float& w1, float& w2, float& w3)
{
    float a0 = v.x, a1 = v.y, a2 = v.z, a3 = v.w;
    if (kk & 1) { float t = a0; a0 = a1; a1 = t; t = a2; a2 = a3; a3 = t; }
    if (kk & 2) { float t = a0; a0 = a2; a2 = t; t = a1; a1 = a3; a3 = t; }
    w0 = a0; w1 = a1; w2 = a2; w3 = a3;
}

// fragment-order STS with kk-rotated issue order (data placement unchanged).
// A-frag layout [kk][gmt(4)][lane]{e0..e3}: 8-way -> 2-way.
__device__ __forceinline__ void stsA(float* p, int arow, int akq, float4 v) {
    const int kk = akq >> 1;
    const int e  = ((akq & 1) << 1) | ((arow >> 3) & 1);
    float* base = p + (size_t)((kk * 4 + (arow >> 4)) * 32 + ((arow & 7) << 2)) * 4 + e;
    float w0, w1, w2, w3;
    rot4(v, kk, w0, w1, w2, w3);
    base[((0 ^ kk) << 2)] = w0;
    base[((1 ^ kk) << 2)] = w1;
    base[((2 ^ kk) << 2)] = w2;
    base[((3 ^ kk) << 2)] = w3;
}
// B-frag layout [kk][gnt(16)][lane]{e0,e1}: 4-way -> conflict-free.
__device__ __forceinline__ void stsB(float* p, int brow, int bkq, float4 v) {
    const int kk = bkq >> 1;
    const int e  = bkq & 1;
    float* base = p + (size_t)((kk * 16 + (brow >> 3)) * 32 + ((brow & 7) << 2)) * 2 + e;
    float w0, w1, w2, w3;
    rot4(v, kk, w0, w1, w2, w3);
    base[((0 ^ kk) << 1)] = w0;
    base[((1 ^ kk) << 1)] = w1;
    base[((2 ^ kk) << 1)] = w2;
    base[((3 ^ kk) << 1)] = w3;
}

__global__ void __launch_bounds__(THREADS, 2) embed_kernel(
    const float* __restrict__ ebg, const float* __restrict__ ebp,
    const float* __restrict__ gw1, const float* __restrict__ gb1,
    const float* __restrict__ gw2, const float* __restrict__ gb2,
    const float* __restrict__ pw1, const float* __restrict__ pb1,
    const float* __restrict__ pw2, const float* __restrict__ pb2)
{
    extern __shared__ char sm[];
    float* miscf = (float*)sm;
    float* b1s   = miscf;                 // [128]
    float* b2s   = miscf + 128;           // [128]
    float* rinvs = miscf + 256;           // [64]
    float* parts = miscf + 320;           // [4][64]
    float* Hf    = (float*)(sm + OFF_HF); // 8192 floats (32KB), A-frag layout

    const int t    = threadIdx.x;
    const int wid  = t >> 5, lane = t & 31;
    const int wm   = wid >> 2, wn = wid & 3;   // wm 0..1, wn 0..3
    const int gm2  = wm * 2,   wn4 = wn * 4;
    const int blk  = blockIdx.x;

    const float *X, *W1, *B1v, *W2, *B2v;
    float* OUT;
    int rowbase;
    if (blk < NBLK_G) {
        X = ebg; W1 = gw1; B1v = gb1; W2 = gw2; B2v = gb2;
        OUT = g_buf; rowbase = blk * TM;
    } else {
        X = ebp; W1 = pw1; B1v = pb1; W2 = pw2; B2v = pb2;
        OUT = p_buf; rowbase = (blk - NBLK_G) * TM;
    }

    if (t < 128) b1s[t] = B1v[t];
    else         b2s[t - 128] = B2v[t - 128];

    // loader indexing: thread covers A rows arow0(+32), B rows arow0+32*i, k-quad akq
    const int arow0 = t >> 3;       // 0..31
    const int akq   = t & 7;
    const float* xptr  = X  + (size_t)(rowbase + arow0) * DIN + akq * 4;
    const float* w1ptr = W1 + (size_t)arow0 * DIN + akq * 4;
    const float* w2ptr = W2 + (size_t)arow0 * Dm  + akq * 4;

    float acc[2][4][4];
#pragma unroll
    for (int a = 0; a < 2; a++)
#pragma unroll
        for (int b = 0; b < 4; b++)
#pragma unroll
            for (int c = 0; c < 4; c++) acc[a][b][c] = 0.f;

    // ---------------- Layer 1: K = 640, 20 chunks of 32, 2-pass ----------
    float4 pax[2], pbx[4];
#pragma unroll
    for (int i = 0; i < 2; i++)
        pax[i] = *(const float4*)(xptr + (size_t)(32 * i) * DIN);
#pragma unroll
    for (int i = 0; i < 4; i++)
        pbx[i] = *(const float4*)(w1ptr + (size_t)(32 * i) * DIN);
    {
        float* S = (float*)(sm + OFF_STG);
#pragma unroll
        for (int i = 0; i < 2; i++) stsA(S, arow0 + 32 * i, akq, pax[i]);
#pragma unroll
        for (int i = 0; i < 4; i++) stsB(S + 2048, arow0 + 32 * i, akq, pbx[i]);
    }
    __syncthreads();

#pragma unroll 1
    for (int c = 0; c < 20; c++) {
        if (c < 19) {
#pragma unroll
            for (int i = 0; i < 2; i++)
                pax[i] = *(const float4*)(xptr + (size_t)(32 * i) * DIN + (c + 1) * 32);
#pragma unroll
            for (int i = 0; i < 4; i++)
                pbx[i] = *(const float4*)(w1ptr + (size_t)(32 * i) * DIN + (c + 1) * 32);
        }
        const float* S = (const float*)(sm + OFF_STG + (c & 1) * STG_SZ);
        gemm_chunk<false>(S, S + 2048, acc, lane, gm2, wn4);
        if (c < 19) {
            float* N = (float*)(sm + OFF_STG + ((c + 1) & 1) * STG_SZ);
#pragma unroll
            for (int i = 0; i < 2; i++) stsA(N, arow0 + 32 * i, akq, pax[i]);
#pragma unroll
            for (int i = 0; i < 4; i++) stsB(N + 2048, arow0 + 32 * i, akq, pbx[i]);
        }
        __syncthreads();
    }

    // ------- L1 epilogue: H = relu(acc + b1) -> fp32 A-frag layout --------
#pragma unroll
    for (int mt = 0; mt < 2; mt++)
#pragma unroll
        for (int nt = 0; nt < 4; nt++)
#pragma unroll
            for (int rr = 0; rr < 4; rr++) {
                const int m = wm * 32 + mt * 16 + (lane >> 2) + 8 * (rr >> 1);
                const int n = wn * 32 + nt * 8 + 2 * (lane & 3) + (rr & 1);
                float y = fmaxf(acc[mt][nt][rr] + b1s[n], 0.f);
                const int idx = ((((n >> 3) * 4 + (m >> 4)) * 32
                                  + (((m & 7) << 2) | (n & 3))) << 2)
                                + (((n & 4) >> 1) | ((m >> 3) & 1));
                Hf[idx] = y;
            }

    // stage B2 chunk 0 (fp32)
#pragma unroll
    for (int i = 0; i < 4; i++)
        pbx[i] = *(const float4*)(w2ptr + (size_t)(32 * i) * Dm);
    {
        float* S = (float*)(sm + OFF_B2);
#pragma unroll
        for (int i = 0; i < 4; i++) stsB(S, arow0 + 32 * i, akq, pbx[i]);
    }

#pragma unroll
    for (int a = 0; a < 2; a++)
#pragma unroll
        for (int b = 0; b < 4; b++)
#pragma unroll
            for (int c = 0; c < 4; c++) acc[a][b][c] = 0.f;
    __syncthreads();

    // ---------------- Layer 2: K = 128, 4 chunks of 32, 3-pass ------------
#pragma unroll 1
    for (int c2 = 0; c2 < 4; c2++) {
        if (c2 < 3) {
#pragma unroll
            for (int i = 0; i < 4; i++)
                pbx[i] = *(const float4*)(w2ptr + (size_t)(32 * i) * Dm + (c2 + 1) * 32);
        }
        const float* S = (const float*)(sm + OFF_B2 + (c2 & 1) * 16384);
        gemm_chunk<true>(Hf + c2 * 2048, S, acc, lane, gm2, wn4);
        if (c2 < 3) {
            float* N = (float*)(sm + OFF_B2 + ((c2 + 1) & 1) * 16384);
#pragma unroll
            for (int i = 0; i < 4; i++) stsB(N, arow0 + 32 * i, akq, pbx[i]);
        }
        __syncthreads();
    }

    // -------- L2 epilogue: bias, row sum-squares, L2 norm, direct store ----
    float s2[2][2] = {{0.f, 0.f}, {0.f, 0.f}};
#pragma unroll
    for (int mt = 0; mt < 2; mt++)
#pragma unroll
        for (int nt = 0; nt < 4; nt++)
#pragma unroll
            for (int rr = 0; rr < 4; rr++) {
                const int n = wn * 32 + nt * 8 + 2 * (lane & 3) + (rr & 1);
                const float y = acc[mt][nt][rr] + b2s[n];
                acc[mt][nt][rr] = y;
                s2[mt][rr >> 1] += y * y;
            }
#pragma unroll
    for (int mt = 0; mt < 2; mt++)
#pragma unroll
        for (int rH = 0; rH < 2; rH++) {
            float v = s2[mt][rH];
            v += __shfl_xor_sync(0xffffffffu, v, 1);
            v += __shfl_xor_sync(0xffffffffu, v, 2);
            if ((lane & 3) == 0) {
                const int m = wm * 32 + mt * 16 + (lane >> 2) + 8 * rH;
                parts[wn * 64 + m] = v;
            }
        }
    __syncthreads();
    if (t < 64)
        rinvs[t] = rsqrtf(parts[t] + parts[64 + t] + parts[128 + t] + parts[192 + t]);
    __syncthreads();

#pragma unroll
    for (int mt = 0; mt < 2; mt++)
#pragma unroll
        for (int rH = 0; rH < 2; rH++) {
            const int m = wm * 32 + mt * 16 + (lane >> 2) + 8 * rH;
            const float rv = rinvs[m];
            float* orow = OUT + (size_t)(rowbase + m) * Dm;
#pragma unroll
            for (int nt = 0; nt < 4; nt++) {
                const int n = wn * 32 + nt * 8 + 2 * (lane & 3);
                float2 y;
                y.x = acc[mt][nt][rH * 2 + 0] * rv;
                y.y = acc[mt][nt][rH * 2 + 1] * rv;
                *(float2*)(orow + n) = y;
            }
        }
}

// ---------------------------------------------------------------------------
// Loss: one WARP per b, all rows in registers, no smem, no block barriers.
// ---------------------------------------------------------------------------
__device__ __forceinline__ float wredsum(float v) {
#pragma unroll
    for (int o = 16; o; o >>= 1) v += __shfl_xor_sync(0xffffffffu, v, o);
    return v;
}
__device__ __forceinline__ float wredmax(float v) {
#pragma unroll
    for (int o = 16; o; o >>= 1) v = fmaxf(v, __shfl_xor_sync(0xffffffffu, v, o));
    return v;
}
__device__ __forceinline__ float symkl4(const float* u, const float* v) {
    const float iT = 1.0f / T_KD;
    float uu[4], vv[4];
    float mu = -1e30f, mv = -1e30f;
#pragma unroll
    for (int q = 0; q < 4; q++) {
        uu[q] = u[q] * iT; vv[q] = v[q] * iT;
        mu = fmaxf(mu, uu[q]); mv = fmaxf(mv, vv[q]);
    }
    mu = wredmax(mu); mv = wredmax(mv);
    float eu[4], ev[4], su = 0.f, sv = 0.f;
#pragma unroll
    for (int q = 0; q < 4; q++) {
        eu[q] = __expf(uu[q] - mu); su += eu[q];
        ev[q] = __expf(vv[q] - mv); sv += ev[q];
    }
    su = wredsum(su); sv = wredsum(sv);
    const float lsu = __logf(su), lsv = __logf(sv);
    const float isu = 1.f / su,  isv = 1.f / sv;
    float a = 0.f;
#pragma unroll
    for (int q = 0; q < 4; q++) {
        const float la = uu[q] - mu - lsu;
        const float lb = vv[q] - mv - lsv;
        a += (eu[q] * isu - ev[q] * isv) * (la - lb);
    }
    return wredsum(a);
}

__global__ void __launch_bounds__(256) loss_kernel() {
    const int warp = threadIdx.x >> 5, lane = threadIdx.x & 31;
    const int b = blockIdx.x * 8 + warp;

    float g[4], pb[4], p[Pn][4];
    *(float4*)g = *(const float4*)(g_buf + (size_t)b * Dm + lane * 4);
#pragma unroll
    for (int l = 0; l < Pn; l++)
        *(float4*)p[l] = *(const float4*)(p_buf + ((size_t)l * Bsz + b) * Dm + lane * 4);

#pragma unroll
    for (int q = 0; q < 4; q++) {
        float s = 0.f;
#pragma unroll
        for (int l = 0; l < Pn; l++) s += p[l][q];
        pb[q] = s * (1.0f / Pn);
    }

    const float vdil = symkl4(g, pb);

    float dcl = 0.f;
#pragma unroll
    for (int l = 0; l < Pn; l++) {
        float du[4], dv[4];
#pragma unroll
        for (int q = 0; q < 4; q++) {
            float a = g[q]  - p[l][q]; du[q] = a * a;
            float d = pb[q] - p[l][q]; dv[q] = d * d;
        }
        dcl += symkl4(du, dv);
    }

    if (lane == 0) {
        const float sc = (T_KD * T_KD) / (float)Dm;
        part_dil[b] = vdil * sc;
        part_dcl[b] = dcl * sc;
    }
}

// Deterministic fixed-order final reduction
__global__ void __launch_bounds__(256) final_kernel(float* out, int out_size) {
    __shared__ float s1[256], s2[256];
    const int t = threadIdx.x;
    float a = 0.f, c = 0.f;
    for (int i = t; i < Bsz; i += 256) { a += part_dil[i]; c += part_dcl[i]; }
    s1[t] = a; s2[t] = c;
    __syncthreads();
#pragma unroll
    for (int o = 128; o > 0; o >>= 1) {
        if (t < o) { s1[t] += s1[t + o]; s2[t] += s2[t + o]; }
        __syncthreads();
    }
    if (t == 0) {
        if (out_size > 0) out[0] = s1[0];
        if (out_size > 1) out[1] = s2[0] * (1.0f / Pn);
    }
}

extern "C" void kernel_launch(void* const* d_in, const int* in_sizes, int n_in,
                              void* d_out, int out_size) {
    (void)in_sizes; (void)n_in;
    const float* ebg = (const float*)d_in[0];
    const float* ebp = (const float*)d_in[1];
    const float* gw1 = (const float*)d_in[3];
    const float* gb1 = (const float*)d_in[4];
    const float* gw2 = (const float*)d_in[5];
    const float* gb2 = (const float*)d_in[6];
    const float* pw1 = (const float*)d_in[7];
    const float* pb1 = (const float*)d_in[8];
    const float* pw2 = (const float*)d_in[9];
    const float* pb2 = (const float*)d_in[10];

    cudaFuncSetAttribute(embed_kernel,
                         cudaFuncAttributeMaxDynamicSharedMemorySize, SMEM_TOTAL);

    embed_kernel<<<NTILES, THREADS, SMEM_TOTAL>>>(
        ebg, ebp, gw1, gb1, gw2, gb2, pw1, pb1, pw2, pb2);
    loss_kernel<<<Bsz / 8, 256>>>();
    final_kernel<<<1, 256>>>((float*)d_out, out_size);
}